// round 3
// baseline (speedup 1.0000x reference)
#include <cuda_runtime.h>
#include <cuda_bf16.h>
#include <math.h>

// Problem constants
#define B_   32
#define LQ_  576
#define LV_  3024
#define C_   1024
#define NH_  16
#define NL_  3
#define NP_  4
#define D_   64   // C_/NH_

// ---------------------------------------------------------------------------
// Scratch (device globals — allocation is forbidden, these are the workaround)
// ---------------------------------------------------------------------------
__device__ float g_v[(size_t)B_ * LV_ * C_];        // value projection   (396 MB)
__device__ float g_off[(size_t)B_ * LQ_ * 384];     // sampling offsets   (28 MB)
__device__ float g_awl[(size_t)B_ * LQ_ * 192];     // attention logits   (14 MB)
__device__ float g_ref[(size_t)B_ * LQ_ * 2];       // reference points
__device__ float g_samp[(size_t)B_ * LQ_ * C_];     // sampled output     (75 MB)

// ---------------------------------------------------------------------------
// SGEMM (NT):  C[m][n] = sum_k A[m][k] * B[n][k] + bias[n]
// A: M x K row-major,  B: N x K row-major (weight), both K-contiguous.
// Tile 128x128x16, 256 threads, 8x8 accum/thread, register-prefetch
// double buffering (global loads for tile kb+1 overlap FMAs of tile kb).
// Assumes M % 128 == 0 and K % 16 == 0 (true for all uses); N bounds-checked.
// ---------------------------------------------------------------------------
#define BM 128
#define BN 128
#define BK 16
#define TM 8
#define TN 8

__device__ __forceinline__
void sgemm_body(const float* __restrict__ A,
                const float* __restrict__ Bw,
                const float* __restrict__ bias,
                float* __restrict__ Cout,
                int M, int N, int K)
{
    __shared__ float As[BK][BM + 4];
    __shared__ float Bs[BK][BN + 4];

    const int tid = threadIdx.x;
    const int m0  = blockIdx.y * BM;
    const int n0  = blockIdx.x * BN;

    const int tx = tid & 15;
    const int ty = tid >> 4;
    const int tr = ty * TM;
    const int tc = tx * TN;

    // loader indexing: each thread loads 2x float4 from A and 2x from B per tile
    const int lr = tid >> 2;        // 0..63 (row within tile, +64 second pass)
    const int lk = (tid & 3) * 4;   // k offset (float4 granularity)

    const float* Ar0 = A  + (size_t)(m0 + lr)      * K + lk;
    const float* Ar1 = A  + (size_t)(m0 + lr + 64) * K + lk;
    const bool   bv0 = (n0 + lr)      < N;
    const bool   bv1 = (n0 + lr + 64) < N;
    const float* Br0 = Bw + (size_t)(n0 + lr)      * K + lk;
    const float* Br1 = Bw + (size_t)(n0 + lr + 64) * K + lk;
    const float4 fz  = make_float4(0.f, 0.f, 0.f, 0.f);

    float acc[TM][TN];
#pragma unroll
    for (int i = 0; i < TM; ++i)
#pragma unroll
        for (int j = 0; j < TN; ++j) acc[i][j] = 0.f;

    // ---- prologue: load tile 0 into smem ----
    {
        const float4 a0 = *(const float4*)(Ar0);
        const float4 a1 = *(const float4*)(Ar1);
        const float4 b0 = bv0 ? *(const float4*)(Br0) : fz;
        const float4 b1 = bv1 ? *(const float4*)(Br1) : fz;
        As[lk + 0][lr] = a0.x; As[lk + 1][lr] = a0.y; As[lk + 2][lr] = a0.z; As[lk + 3][lr] = a0.w;
        As[lk + 0][lr + 64] = a1.x; As[lk + 1][lr + 64] = a1.y; As[lk + 2][lr + 64] = a1.z; As[lk + 3][lr + 64] = a1.w;
        Bs[lk + 0][lr] = b0.x; Bs[lk + 1][lr] = b0.y; Bs[lk + 2][lr] = b0.z; Bs[lk + 3][lr] = b0.w;
        Bs[lk + 0][lr + 64] = b1.x; Bs[lk + 1][lr + 64] = b1.y; Bs[lk + 2][lr + 64] = b1.z; Bs[lk + 3][lr + 64] = b1.w;
    }
    __syncthreads();

    for (int kb = BK; kb <= K; kb += BK) {
        // ---- prefetch next tile into registers (overlaps FMA loop) ----
        float4 na0, na1, nb0, nb1;
        const bool have_next = (kb < K);
        if (have_next) {
            na0 = *(const float4*)(Ar0 + kb);
            na1 = *(const float4*)(Ar1 + kb);
            nb0 = bv0 ? *(const float4*)(Br0 + kb) : fz;
            nb1 = bv1 ? *(const float4*)(Br1 + kb) : fz;
        }

        // ---- compute current tile ----
#pragma unroll
        for (int k = 0; k < BK; ++k) {
            float ra[TM], rb[TN];
            const float4 a0 = *(const float4*)&As[k][tr];
            const float4 a1 = *(const float4*)&As[k][tr + 4];
            const float4 b0 = *(const float4*)&Bs[k][tc];
            const float4 b1 = *(const float4*)&Bs[k][tc + 4];
            ra[0] = a0.x; ra[1] = a0.y; ra[2] = a0.z; ra[3] = a0.w;
            ra[4] = a1.x; ra[5] = a1.y; ra[6] = a1.z; ra[7] = a1.w;
            rb[0] = b0.x; rb[1] = b0.y; rb[2] = b0.z; rb[3] = b0.w;
            rb[4] = b1.x; rb[5] = b1.y; rb[6] = b1.z; rb[7] = b1.w;
#pragma unroll
            for (int i = 0; i < TM; ++i)
#pragma unroll
                for (int j = 0; j < TN; ++j)
                    acc[i][j] = fmaf(ra[i], rb[j], acc[i][j]);
        }

        if (have_next) {
            __syncthreads();
            As[lk + 0][lr] = na0.x; As[lk + 1][lr] = na0.y; As[lk + 2][lr] = na0.z; As[lk + 3][lr] = na0.w;
            As[lk + 0][lr + 64] = na1.x; As[lk + 1][lr + 64] = na1.y; As[lk + 2][lr + 64] = na1.z; As[lk + 3][lr + 64] = na1.w;
            Bs[lk + 0][lr] = nb0.x; Bs[lk + 1][lr] = nb0.y; Bs[lk + 2][lr] = nb0.z; Bs[lk + 3][lr] = nb0.w;
            Bs[lk + 0][lr + 64] = nb1.x; Bs[lk + 1][lr + 64] = nb1.y; Bs[lk + 2][lr + 64] = nb1.z; Bs[lk + 3][lr + 64] = nb1.w;
            __syncthreads();
        }
    }

    // ---- epilogue: bias + store ----
#pragma unroll
    for (int i = 0; i < TM; ++i) {
        const size_t rowOff = (size_t)(m0 + tr + i) * N;
#pragma unroll
        for (int j = 0; j < TN; ++j) {
            const int n = n0 + tc + j;
            if (n < N)
                Cout[rowOff + n] = acc[i][j] + bias[n];
        }
    }
}

// --- per-stage wrappers: bind scratch symbols in device code, so that
//     kernel_launch contains kernel launches ONLY (no host-side symbol APIs).
__global__ __launch_bounds__(256, 2)
void gemm_value(const float* __restrict__ value, const float* __restrict__ Wv,
                const float* __restrict__ bv)
{ sgemm_body(value, Wv, bv, g_v, B_ * LV_, C_, C_); }

__global__ __launch_bounds__(256, 2)
void gemm_off(const float* __restrict__ query, const float* __restrict__ Wo,
              const float* __restrict__ bo)
{ sgemm_body(query, Wo, bo, g_off, B_ * LQ_, 384, C_); }

__global__ __launch_bounds__(256, 2)
void gemm_aw(const float* __restrict__ query, const float* __restrict__ Ww,
             const float* __restrict__ bw)
{ sgemm_body(query, Ww, bw, g_awl, B_ * LQ_, 192, C_); }

__global__ __launch_bounds__(256, 2)
void gemm_out(const float* __restrict__ Wout, const float* __restrict__ bout,
              float* __restrict__ out)
{ sgemm_body(g_samp, Wout, bout, out, B_ * LQ_, C_, C_); }

// ---------------------------------------------------------------------------
// Reference-point kernel: one block per batch, 576 threads.
// ref[b,q] = (mean(rp[b,0:2304]) + rp[b,2304+q] + bilinear_up(rp[b,2880:3024])[q]) / 3
// ---------------------------------------------------------------------------
__global__ void ref_kernel(const float* __restrict__ rp)
{
    const int b = blockIdx.x;
    const int t = threadIdx.x;   // 0..575

    __shared__ float sx[576], sy[576];
    __shared__ float p1x, p1y;

    const float* rpb = rp + (size_t)b * LV_ * 2;

    // partial sums for mean over first 2304 points (4 per thread)
    float ax = 0.f, ay = 0.f;
#pragma unroll
    for (int j = 0; j < 4; ++j) {
        const int idx = t * 4 + j;
        ax += rpb[idx * 2 + 0];
        ay += rpb[idx * 2 + 1];
    }
    sx[t] = ax; sy[t] = ay;
    __syncthreads();
    if (t == 0) {
        float X = 0.f, Y = 0.f;
        for (int i = 0; i < 576; ++i) { X += sx[i]; Y += sy[i]; }
        p1x = X * (1.f / 2304.f);
        p1y = Y * (1.f / 2304.f);
    }
    __syncthreads();

    // p2: mid-level points
    const float p2x = rpb[(2304 + t) * 2 + 0];
    const float p2y = rpb[(2304 + t) * 2 + 1];

    // p3: bilinear upsample 12x12 -> 24x24 (half-pixel centers, clamped edges —
    // matches jax.image.resize weight renormalization at borders for scale 0.5)
    const int oy = t / 24;
    const int ox = t % 24;
    const float fy = oy * 0.5f - 0.25f;
    const float fx = ox * 0.5f - 0.25f;
    int y0 = (int)floorf(fy);
    int x0 = (int)floorf(fx);
    const float wy = fy - (float)y0;
    const float wx = fx - (float)x0;
    int y1 = y0 + 1, x1 = x0 + 1;
    y0 = min(max(y0, 0), 11); y1 = min(max(y1, 0), 11);
    x0 = min(max(x0, 0), 11); x1 = min(max(x1, 0), 11);

    const float* g = rpb + 2880 * 2;
    const float v00x = g[(y0 * 12 + x0) * 2 + 0], v00y = g[(y0 * 12 + x0) * 2 + 1];
    const float v01x = g[(y0 * 12 + x1) * 2 + 0], v01y = g[(y0 * 12 + x1) * 2 + 1];
    const float v10x = g[(y1 * 12 + x0) * 2 + 0], v10y = g[(y1 * 12 + x0) * 2 + 1];
    const float v11x = g[(y1 * 12 + x1) * 2 + 0], v11y = g[(y1 * 12 + x1) * 2 + 1];

    const float p3x = (1.f - wy) * ((1.f - wx) * v00x + wx * v01x)
                    +        wy  * ((1.f - wx) * v10x + wx * v11x);
    const float p3y = (1.f - wy) * ((1.f - wx) * v00y + wx * v01y)
                    +        wy  * ((1.f - wx) * v10y + wx * v11y);

    const size_t o = ((size_t)b * LQ_ + t) * 2;
    g_ref[o + 0] = (p1x + p2x + p3x) * (1.f / 3.f);
    g_ref[o + 1] = (p1y + p2y + p3y) * (1.f / 3.f);
}

// ---------------------------------------------------------------------------
// Fused softmax + nearest-cell gather + weighted-sum.
// Block: 256 threads = 4 heads x 64 channels. Grid: B*LQ*(NH/4).
// ---------------------------------------------------------------------------
__global__ __launch_bounds__(256)
void sample_kernel(const int* __restrict__ shapes,
                   const int* __restrict__ starts)
{
    const int blk = blockIdx.x;
    const int hg  = blk & 3;                 // head group 0..3 (NH/4 = 4)
    const int bq  = blk >> 2;                // b*LQ + q
    const int hl  = threadIdx.x >> 6;        // 0..3
    const int d   = threadIdx.x & 63;
    const int h   = hg * 4 + hl;
    const int b   = bq / LQ_;

    const float r0 = g_ref[(size_t)bq * 2 + 0];
    const float r1 = g_ref[(size_t)bq * 2 + 1];

    const float* offp = g_off + (size_t)bq * 384 + h * 24;
    const float* lg   = g_awl + (size_t)bq * 192 + h * 12;

    // softmax over 12 (redundant across threads of a head; broadcast loads)
    float e[12];
    float mx = -1e30f;
#pragma unroll
    for (int i = 0; i < 12; ++i) { e[i] = lg[i]; mx = fmaxf(mx, e[i]); }
    float s = 0.f;
#pragma unroll
    for (int i = 0; i < 12; ++i) { e[i] = expf(e[i] - mx); s += e[i]; }
    const float inv = 1.f / s;

    float acc = 0.f;
#pragma unroll
    for (int l = 0; l < NL_; ++l) {
        const int H  = shapes[l * 2 + 0];
        const int W  = shapes[l * 2 + 1];
        const int st = starts[l];
#pragma unroll
        for (int p = 0; p < NP_; ++p) {
            const int i = l * NP_ + p;
            float c0 = offp[i * 2 + 0] + r0;
            float c1 = offp[i * 2 + 1] + r1;
            // pre-clamp to keep int cast safe; equivalent to clip(floor(c),0,H-1)
            c0 = fminf(fmaxf(c0, -1.0f), (float)H);
            c1 = fminf(fmaxf(c1, -1.0f), (float)W);
            int x = (int)floorf(c0); x = min(max(x, 0), H - 1);
            int y = (int)floorf(c1); y = min(max(y, 0), W - 1);
            const int pos = st + x * W + y;
            const float gv = g_v[(((size_t)b * LV_ + pos) * NH_ + h) * D_ + d];
            acc = fmaf(e[i] * inv, gv, acc);
        }
    }
    g_samp[(size_t)bq * C_ + h * D_ + d] = acc;
}

// ---------------------------------------------------------------------------
// Launch — kernel launches ONLY (graph-capture safe, allocation-free)
// ---------------------------------------------------------------------------
extern "C" void kernel_launch(void* const* d_in, const int* in_sizes, int n_in,
                              void* d_out, int out_size)
{
    const float* query   = (const float*)d_in[0];
    const float* refpts  = (const float*)d_in[1];
    const float* value   = (const float*)d_in[2];
    const int*   shapes  = (const int*)  d_in[3];
    const int*   starts  = (const int*)  d_in[4];
    const float* Wv      = (const float*)d_in[5];
    const float* bv      = (const float*)d_in[6];
    const float* Wo      = (const float*)d_in[7];
    const float* bo      = (const float*)d_in[8];
    const float* Ww      = (const float*)d_in[9];
    const float* bw      = (const float*)d_in[10];
    const float* Wout    = (const float*)d_in[11];
    const float* bout    = (const float*)d_in[12];
    float* out = (float*)d_out;

    const int Mv = B_ * LV_;   // 96768
    const int Mq = B_ * LQ_;   // 18432

    // 1) value projection: v = value @ Wv^T + bv
    gemm_value<<<dim3(C_ / BN, Mv / BM), 256>>>(value, Wv, bv);
    // 2) offsets: off = query @ Wo^T + bo   (N = 384)
    gemm_off<<<dim3((384 + BN - 1) / BN, Mq / BM), 256>>>(query, Wo, bo);
    // 3) attention logits: query @ Ww^T + bw   (N = 192)
    gemm_aw<<<dim3((192 + BN - 1) / BN, Mq / BM), 256>>>(query, Ww, bw);
    // 4) reference points
    ref_kernel<<<B_, LQ_>>>(refpts);
    // 5) fused softmax + gather + weighted sum
    sample_kernel<<<B_ * LQ_ * (NH_ / 4), 256>>>(shapes, starts);
    // 6) output projection: out = samp @ Wout^T + bout
    gemm_out<<<dim3(C_ / BN, Mq / BM), 256>>>(Wout, bout, out);
}

// round 8
// speedup vs baseline: 2.1252x; 2.1252x over previous
#include <cuda_runtime.h>
#include <cuda_bf16.h>
#include <math.h>
#include <stdint.h>

// Problem constants
#define B_   32
#define LQ_  576
#define LV_  3024
#define C_   1024
#define NH_  16
#define NL_  3
#define NP_  4
#define D_   64   // C_/NH_

// ---------------------------------------------------------------------------
// Scratch (device globals — allocation is forbidden, these are the workaround)
// ---------------------------------------------------------------------------
__device__ float g_v[(size_t)B_ * LV_ * C_];        // value projection   (396 MB)
__device__ float g_off[(size_t)B_ * LQ_ * 384];     // sampling offsets   (28 MB)
__device__ float g_awl[(size_t)B_ * LQ_ * 192];     // attention logits   (14 MB)
__device__ float g_ref[(size_t)B_ * LQ_ * 2];       // reference points
__device__ float g_samp[(size_t)B_ * LQ_ * C_];     // sampled output     (75 MB)

// tf32 round: PTX cvt.rna.tf32.f32 requires a .b32 destination register.
__device__ __forceinline__ float to_tf32(float x) {
    unsigned r;
    asm("cvt.rna.tf32.f32 %0, %1;" : "=r"(r) : "f"(x));
    return __uint_as_float(r);
}
__device__ __forceinline__ unsigned fu(float x) { return __float_as_uint(x); }

// ---------------------------------------------------------------------------
// TF32 tensor-core GEMM (NT):  C[m][n] = sum_k A[m][k]*B[n][k] + bias[n]
// Fixed N = K = 1024 (tile-exact); M a multiple of 128.
// Tile 128x128x16, 256 threads (8 warps, 4x2), warp tile 32x64 via m16n8k8.
// Smem: k-major, stride 136, column XOR-swizzled by 8*(k>>2) —
// conflict-free for both transposed stores and fragment loads.
// ---------------------------------------------------------------------------
#define VBM 128
#define VBN 128
#define VBK 16
#define VAS 136   // row stride (floats) for both tiles

__device__ __forceinline__
void gemm_tf32_body(const float* __restrict__ A, const float* __restrict__ Bw,
                    const float* __restrict__ bias, float* __restrict__ Cout)
{
    const int N = C_, K = C_;
    __shared__ float As[VBK * VAS];
    __shared__ float Bs[VBK * VAS];

    const int tid   = threadIdx.x;
    const int m0    = blockIdx.y * VBM;
    const int n0    = blockIdx.x * VBN;
    const int warp  = tid >> 5;
    const int lane  = tid & 31;
    const int group = lane >> 2;    // 0..7
    const int tig   = lane & 3;     // 0..3
    const int wm    = warp & 3;     // 0..3 (M direction)
    const int wn    = warp >> 2;    // 0..1 (N direction)

    // loader mapping: each thread loads 2x float4 from A and B per K-tile
    const int lr = tid >> 2;        // 0..63 (tile row; +64 second half)
    const int lk = (tid & 3) * 4;   // k offset 0,4,8,12
    const int t4 = tid & 3;         // = lk>>2 -> swizzle mask index

    const float* Ar0 = A  + (size_t)(m0 + lr)      * K + lk;
    const float* Ar1 = A  + (size_t)(m0 + lr + 64) * K + lk;
    const float* Br0 = Bw + (size_t)(n0 + lr)      * K + lk;
    const float* Br1 = Bw + (size_t)(n0 + lr + 64) * K + lk;

    const int scol0 = lr        ^ (t4 << 3);   // swizzled store column, half 0
    const int scol1 = (lr + 64) ^ (t4 << 3);   // half 1

    float acc[2][8][4];
#pragma unroll
    for (int i = 0; i < 2; ++i)
#pragma unroll
        for (int j = 0; j < 8; ++j)
#pragma unroll
            for (int c = 0; c < 4; ++c) acc[i][j][c] = 0.f;

    // ---- store a (va0,va1 | vb0,vb1) pair into swizzled smem ----
    auto store_tiles = [&](const float4& a0, const float4& a1,
                           const float4& b0, const float4& b1) {
        As[(lk + 0) * VAS + scol0] = to_tf32(a0.x);
        As[(lk + 1) * VAS + scol0] = to_tf32(a0.y);
        As[(lk + 2) * VAS + scol0] = to_tf32(a0.z);
        As[(lk + 3) * VAS + scol0] = to_tf32(a0.w);
        As[(lk + 0) * VAS + scol1] = to_tf32(a1.x);
        As[(lk + 1) * VAS + scol1] = to_tf32(a1.y);
        As[(lk + 2) * VAS + scol1] = to_tf32(a1.z);
        As[(lk + 3) * VAS + scol1] = to_tf32(a1.w);
        Bs[(lk + 0) * VAS + scol0] = to_tf32(b0.x);
        Bs[(lk + 1) * VAS + scol0] = to_tf32(b0.y);
        Bs[(lk + 2) * VAS + scol0] = to_tf32(b0.z);
        Bs[(lk + 3) * VAS + scol0] = to_tf32(b0.w);
        Bs[(lk + 0) * VAS + scol1] = to_tf32(b1.x);
        Bs[(lk + 1) * VAS + scol1] = to_tf32(b1.y);
        Bs[(lk + 2) * VAS + scol1] = to_tf32(b1.z);
        Bs[(lk + 3) * VAS + scol1] = to_tf32(b1.w);
    };

    // ---- prologue: tile 0 ----
    {
        const float4 a0 = *(const float4*)(Ar0);
        const float4 a1 = *(const float4*)(Ar1);
        const float4 b0 = *(const float4*)(Br0);
        const float4 b1 = *(const float4*)(Br1);
        store_tiles(a0, a1, b0, b1);
    }
    __syncthreads();

    for (int kb = VBK; kb <= K; kb += VBK) {
        float4 na0, na1, nb0, nb1;
        const bool have_next = (kb < K);
        if (have_next) {
            na0 = *(const float4*)(Ar0 + kb);
            na1 = *(const float4*)(Ar1 + kb);
            nb0 = *(const float4*)(Br0 + kb);
            nb1 = *(const float4*)(Br1 + kb);
        }

        // ---- compute current tile: two k-steps of 8 ----
#pragma unroll
        for (int ks = 0; ks < 2; ++ks) {
            const int kk = ks * 8;
            const int mlo = ((kk >> 2) + 0) << 3;   // swizzle mask, rows kk+tig
            const int mhi = ((kk >> 2) + 1) << 3;   // rows kk+4+tig

            unsigned af[2][4];
#pragma unroll
            for (int i = 0; i < 2; ++i) {
                const int rb = wm * 32 + i * 16 + group;
                af[i][0] = fu(As[(kk + tig)     * VAS + ((rb)     ^ mlo)]);
                af[i][1] = fu(As[(kk + tig)     * VAS + ((rb + 8) ^ mlo)]);
                af[i][2] = fu(As[(kk + tig + 4) * VAS + ((rb)     ^ mhi)]);
                af[i][3] = fu(As[(kk + tig + 4) * VAS + ((rb + 8) ^ mhi)]);
            }
#pragma unroll
            for (int j = 0; j < 8; ++j) {
                const int cb = wn * 64 + j * 8 + group;
                const unsigned b0 = fu(Bs[(kk + tig)     * VAS + (cb ^ mlo)]);
                const unsigned b1 = fu(Bs[(kk + tig + 4) * VAS + (cb ^ mhi)]);
#pragma unroll
                for (int i = 0; i < 2; ++i) {
                    asm volatile(
                        "mma.sync.aligned.m16n8k8.row.col.f32.tf32.tf32.f32 "
                        "{%0,%1,%2,%3}, {%4,%5,%6,%7}, {%8,%9}, {%0,%1,%2,%3};"
                        : "+f"(acc[i][j][0]), "+f"(acc[i][j][1]),
                          "+f"(acc[i][j][2]), "+f"(acc[i][j][3])
                        : "r"(af[i][0]), "r"(af[i][1]), "r"(af[i][2]), "r"(af[i][3]),
                          "r"(b0), "r"(b1));
                }
            }
        }

        if (have_next) {
            __syncthreads();
            store_tiles(na0, na1, nb0, nb1);
            __syncthreads();
        }
    }

    // ---- epilogue: bias + float2 stores ----
#pragma unroll
    for (int i = 0; i < 2; ++i) {
        const int r0 = m0 + wm * 32 + i * 16 + group;
#pragma unroll
        for (int j = 0; j < 8; ++j) {
            const int cn = n0 + wn * 64 + j * 8 + tig * 2;
            const float bz0 = bias[cn], bz1 = bias[cn + 1];
            float2 v01 = make_float2(acc[i][j][0] + bz0, acc[i][j][1] + bz1);
            float2 v23 = make_float2(acc[i][j][2] + bz0, acc[i][j][3] + bz1);
            *(float2*)&Cout[(size_t)r0 * N + cn]       = v01;
            *(float2*)&Cout[(size_t)(r0 + 8) * N + cn] = v23;
        }
    }
}

__global__ __launch_bounds__(256, 2)
void gemm_value_tf32(const float* __restrict__ value, const float* __restrict__ Wv,
                     const float* __restrict__ bv)
{ gemm_tf32_body(value, Wv, bv, g_v); }

__global__ __launch_bounds__(256, 2)
void gemm_out_tf32(const float* __restrict__ Wout, const float* __restrict__ bout,
                   float* __restrict__ out)
{ gemm_tf32_body(g_samp, Wout, bout, out); }

// ---------------------------------------------------------------------------
// FP32 SGEMM (NT) — kept for off/aw projections (they feed floor(): a 5e-4
// coordinate error flips nearest-cell selections, so these stay full fp32).
// Tile 128x128x16, 256 threads, 8x8/thread, register-prefetch DB.
// ---------------------------------------------------------------------------
#define BM 128
#define BN 128
#define BK 16
#define TM 8
#define TN 8

__device__ __forceinline__
void sgemm_body(const float* __restrict__ A,
                const float* __restrict__ Bw,
                const float* __restrict__ bias,
                float* __restrict__ Cout,
                int M, int N, int K)
{
    __shared__ float As[BK][BM + 4];
    __shared__ float Bs[BK][BN + 4];

    const int tid = threadIdx.x;
    const int m0  = blockIdx.y * BM;
    const int n0  = blockIdx.x * BN;

    const int tx = tid & 15;
    const int ty = tid >> 4;
    const int tr = ty * TM;
    const int tc = tx * TN;

    const int lr = tid >> 2;
    const int lk = (tid & 3) * 4;

    const float* Ar0 = A  + (size_t)(m0 + lr)      * K + lk;
    const float* Ar1 = A  + (size_t)(m0 + lr + 64) * K + lk;
    const bool   bv0 = (n0 + lr)      < N;
    const bool   bv1 = (n0 + lr + 64) < N;
    const float* Br0 = Bw + (size_t)(n0 + lr)      * K + lk;
    const float* Br1 = Bw + (size_t)(n0 + lr + 64) * K + lk;
    const float4 fz  = make_float4(0.f, 0.f, 0.f, 0.f);

    float acc[TM][TN];
#pragma unroll
    for (int i = 0; i < TM; ++i)
#pragma unroll
        for (int j = 0; j < TN; ++j) acc[i][j] = 0.f;

    {
        const float4 a0 = *(const float4*)(Ar0);
        const float4 a1 = *(const float4*)(Ar1);
        const float4 b0 = bv0 ? *(const float4*)(Br0) : fz;
        const float4 b1 = bv1 ? *(const float4*)(Br1) : fz;
        As[lk + 0][lr] = a0.x; As[lk + 1][lr] = a0.y; As[lk + 2][lr] = a0.z; As[lk + 3][lr] = a0.w;
        As[lk + 0][lr + 64] = a1.x; As[lk + 1][lr + 64] = a1.y; As[lk + 2][lr + 64] = a1.z; As[lk + 3][lr + 64] = a1.w;
        Bs[lk + 0][lr] = b0.x; Bs[lk + 1][lr] = b0.y; Bs[lk + 2][lr] = b0.z; Bs[lk + 3][lr] = b0.w;
        Bs[lk + 0][lr + 64] = b1.x; Bs[lk + 1][lr + 64] = b1.y; Bs[lk + 2][lr + 64] = b1.z; Bs[lk + 3][lr + 64] = b1.w;
    }
    __syncthreads();

    for (int kb = BK; kb <= K; kb += BK) {
        float4 na0, na1, nb0, nb1;
        const bool have_next = (kb < K);
        if (have_next) {
            na0 = *(const float4*)(Ar0 + kb);
            na1 = *(const float4*)(Ar1 + kb);
            nb0 = bv0 ? *(const float4*)(Br0 + kb) : fz;
            nb1 = bv1 ? *(const float4*)(Br1 + kb) : fz;
        }

#pragma unroll
        for (int k = 0; k < BK; ++k) {
            float ra[TM], rb[TN];
            const float4 a0 = *(const float4*)&As[k][tr];
            const float4 a1 = *(const float4*)&As[k][tr + 4];
            const float4 b0 = *(const float4*)&Bs[k][tc];
            const float4 b1 = *(const float4*)&Bs[k][tc + 4];
            ra[0] = a0.x; ra[1] = a0.y; ra[2] = a0.z; ra[3] = a0.w;
            ra[4] = a1.x; ra[5] = a1.y; ra[6] = a1.z; ra[7] = a1.w;
            rb[0] = b0.x; rb[1] = b0.y; rb[2] = b0.z; rb[3] = b0.w;
            rb[4] = b1.x; rb[5] = b1.y; rb[6] = b1.z; rb[7] = b1.w;
#pragma unroll
            for (int i = 0; i < TM; ++i)
#pragma unroll
                for (int j = 0; j < TN; ++j)
                    acc[i][j] = fmaf(ra[i], rb[j], acc[i][j]);
        }

        if (have_next) {
            __syncthreads();
            As[lk + 0][lr] = na0.x; As[lk + 1][lr] = na0.y; As[lk + 2][lr] = na0.z; As[lk + 3][lr] = na0.w;
            As[lk + 0][lr + 64] = na1.x; As[lk + 1][lr + 64] = na1.y; As[lk + 2][lr + 64] = na1.z; As[lk + 3][lr + 64] = na1.w;
            Bs[lk + 0][lr] = nb0.x; Bs[lk + 1][lr] = nb0.y; Bs[lk + 2][lr] = nb0.z; Bs[lk + 3][lr] = nb0.w;
            Bs[lk + 0][lr + 64] = nb1.x; Bs[lk + 1][lr + 64] = nb1.y; Bs[lk + 2][lr + 64] = nb1.z; Bs[lk + 3][lr + 64] = nb1.w;
            __syncthreads();
        }
    }

#pragma unroll
    for (int i = 0; i < TM; ++i) {
        const size_t rowOff = (size_t)(m0 + tr + i) * N;
#pragma unroll
        for (int j = 0; j < TN; ++j) {
            const int n = n0 + tc + j;
            if (n < N)
                Cout[rowOff + n] = acc[i][j] + bias[n];
        }
    }
}

__global__ __launch_bounds__(256, 2)
void gemm_off(const float* __restrict__ query, const float* __restrict__ Wo,
              const float* __restrict__ bo)
{ sgemm_body(query, Wo, bo, g_off, B_ * LQ_, 384, C_); }

__global__ __launch_bounds__(256, 2)
void gemm_aw(const float* __restrict__ query, const float* __restrict__ Ww,
             const float* __restrict__ bw)
{ sgemm_body(query, Ww, bw, g_awl, B_ * LQ_, 192, C_); }

// ---------------------------------------------------------------------------
// Reference-point kernel: one block per batch, 576 threads.
// ---------------------------------------------------------------------------
__global__ void ref_kernel(const float* __restrict__ rp)
{
    const int b = blockIdx.x;
    const int t = threadIdx.x;   // 0..575

    __shared__ float sx[576], sy[576];
    __shared__ float p1x, p1y;

    const float* rpb = rp + (size_t)b * LV_ * 2;

    float ax = 0.f, ay = 0.f;
#pragma unroll
    for (int j = 0; j < 4; ++j) {
        const int idx = t * 4 + j;
        ax += rpb[idx * 2 + 0];
        ay += rpb[idx * 2 + 1];
    }
    sx[t] = ax; sy[t] = ay;
    __syncthreads();
    if (t == 0) {
        float X = 0.f, Y = 0.f;
        for (int i = 0; i < 576; ++i) { X += sx[i]; Y += sy[i]; }
        p1x = X * (1.f / 2304.f);
        p1y = Y * (1.f / 2304.f);
    }
    __syncthreads();

    const float p2x = rpb[(2304 + t) * 2 + 0];
    const float p2y = rpb[(2304 + t) * 2 + 1];

    const int oy = t / 24;
    const int ox = t % 24;
    const float fy = oy * 0.5f - 0.25f;
    const float fx = ox * 0.5f - 0.25f;
    int y0 = (int)floorf(fy);
    int x0 = (int)floorf(fx);
    const float wy = fy - (float)y0;
    const float wx = fx - (float)x0;
    int y1 = y0 + 1, x1 = x0 + 1;
    y0 = min(max(y0, 0), 11); y1 = min(max(y1, 0), 11);
    x0 = min(max(x0, 0), 11); x1 = min(max(x1, 0), 11);

    const float* g = rpb + 2880 * 2;
    const float v00x = g[(y0 * 12 + x0) * 2 + 0], v00y = g[(y0 * 12 + x0) * 2 + 1];
    const float v01x = g[(y0 * 12 + x1) * 2 + 0], v01y = g[(y0 * 12 + x1) * 2 + 1];
    const float v10x = g[(y1 * 12 + x0) * 2 + 0], v10y = g[(y1 * 12 + x0) * 2 + 1];
    const float v11x = g[(y1 * 12 + x1) * 2 + 0], v11y = g[(y1 * 12 + x1) * 2 + 1];

    const float p3x = (1.f - wy) * ((1.f - wx) * v00x + wx * v01x)
                    +        wy  * ((1.f - wx) * v10x + wx * v11x);
    const float p3y = (1.f - wy) * ((1.f - wx) * v00y + wx * v01y)
                    +        wy  * ((1.f - wx) * v10y + wx * v11y);

    const size_t o = ((size_t)b * LQ_ + t) * 2;
    g_ref[o + 0] = (p1x + p2x + p3x) * (1.f / 3.f);
    g_ref[o + 1] = (p1y + p2y + p3y) * (1.f / 3.f);
}

// ---------------------------------------------------------------------------
// Fused softmax + nearest-cell gather + weighted-sum.
// Block: 256 threads = 4 heads x 64 channels. Grid: B*LQ*(NH/4).
// ---------------------------------------------------------------------------
__global__ __launch_bounds__(256)
void sample_kernel(const int* __restrict__ shapes,
                   const int* __restrict__ starts)
{
    const int blk = blockIdx.x;
    const int hg  = blk & 3;
    const int bq  = blk >> 2;
    const int hl  = threadIdx.x >> 6;
    const int d   = threadIdx.x & 63;
    const int h   = hg * 4 + hl;
    const int b   = bq / LQ_;

    const float r0 = g_ref[(size_t)bq * 2 + 0];
    const float r1 = g_ref[(size_t)bq * 2 + 1];

    const float* offp = g_off + (size_t)bq * 384 + h * 24;
    const float* lg   = g_awl + (size_t)bq * 192 + h * 12;

    float e[12];
    float mx = -1e30f;
#pragma unroll
    for (int i = 0; i < 12; ++i) { e[i] = lg[i]; mx = fmaxf(mx, e[i]); }
    float s = 0.f;
#pragma unroll
    for (int i = 0; i < 12; ++i) { e[i] = expf(e[i] - mx); s += e[i]; }
    const float inv = 1.f / s;

    float acc = 0.f;
#pragma unroll
    for (int l = 0; l < NL_; ++l) {
        const int H  = shapes[l * 2 + 0];
        const int W  = shapes[l * 2 + 1];
        const int st = starts[l];
#pragma unroll
        for (int p = 0; p < NP_; ++p) {
            const int i = l * NP_ + p;
            float c0 = offp[i * 2 + 0] + r0;
            float c1 = offp[i * 2 + 1] + r1;
            c0 = fminf(fmaxf(c0, -1.0f), (float)H);
            c1 = fminf(fmaxf(c1, -1.0f), (float)W);
            int x = (int)floorf(c0); x = min(max(x, 0), H - 1);
            int y = (int)floorf(c1); y = min(max(y, 0), W - 1);
            const int pos = st + x * W + y;
            const float gv = g_v[(((size_t)b * LV_ + pos) * NH_ + h) * D_ + d];
            acc = fmaf(e[i] * inv, gv, acc);
        }
    }
    g_samp[(size_t)bq * C_ + h * D_ + d] = acc;
}

// ---------------------------------------------------------------------------
// Launch — kernel launches ONLY (graph-capture safe, allocation-free)
// ---------------------------------------------------------------------------
extern "C" void kernel_launch(void* const* d_in, const int* in_sizes, int n_in,
                              void* d_out, int out_size)
{
    const float* query   = (const float*)d_in[0];
    const float* refpts  = (const float*)d_in[1];
    const float* value   = (const float*)d_in[2];
    const int*   shapes  = (const int*)  d_in[3];
    const int*   starts  = (const int*)  d_in[4];
    const float* Wv      = (const float*)d_in[5];
    const float* bv      = (const float*)d_in[6];
    const float* Wo      = (const float*)d_in[7];
    const float* bo      = (const float*)d_in[8];
    const float* Ww      = (const float*)d_in[9];
    const float* bw      = (const float*)d_in[10];
    const float* Wout    = (const float*)d_in[11];
    const float* bout    = (const float*)d_in[12];
    float* out = (float*)d_out;

    const int Mv = B_ * LV_;   // 96768
    const int Mq = B_ * LQ_;   // 18432

    // 1) value projection (tf32 tensor cores): v = value @ Wv^T + bv
    gemm_value_tf32<<<dim3(C_ / VBN, Mv / VBM), 256>>>(value, Wv, bv);
    // 2) offsets (fp32 — feeds floor(), precision-critical)
    gemm_off<<<dim3((384 + BN - 1) / BN, Mq / BM), 256>>>(query, Wo, bo);
    // 3) attention logits (fp32)
    gemm_aw<<<dim3((192 + BN - 1) / BN, Mq / BM), 256>>>(query, Ww, bw);
    // 4) reference points
    ref_kernel<<<B_, LQ_>>>(refpts);
    // 5) fused softmax + gather + weighted sum
    sample_kernel<<<B_ * LQ_ * (NH_ / 4), 256>>>(shapes, starts);
    // 6) output projection (tf32 tensor cores): out = samp @ Wout^T + bout
    gemm_out_tf32<<<dim3(C_ / VBN, Mq / VBM), 256>>>(Wout, bout, out);
}